// round 1
// baseline (speedup 1.0000x reference)
#include <cuda_runtime.h>

#define HID   128
#define SEQ   512
#define BATCH 1024
#define BT    7
#define NCTA  147
#define G3H   (3*HID)                    // 384

#define W4_FLOATS (G3H*HID)              // 49152 floats = 192KB
#define H_OFF     W4_FLOATS              // h state: BT*HID floats
#define V_OFF     (H_OFF + BT*HID)       // v double buffer: 2*BT*2
#define P_OFF     (V_OFF + 2*BT*2)       // x_pred partials: 4 warps * BT * 2
#define SMEM_FLOATS (P_OFF + 4*BT*2)
#define SMEM_BYTES  (SMEM_FLOATS*4)

typedef unsigned long long u64t;
typedef unsigned int u32t;

__device__ __forceinline__ u32t smem_u32(const void* p){
  u32t a; asm("{ .reg .u64 t; cvta.to.shared.u64 t, %1; cvt.u32.u64 %0, t; }":"=r"(a):"l"(p));
  return a;
}
__device__ __forceinline__ u64t pk2(float lo, float hi){
  u64t r; asm("mov.b64 %0,{%1,%2};":"=l"(r):"f"(lo),"f"(hi)); return r;
}
__device__ __forceinline__ float psum(u64t p){
  float lo,hi; asm("mov.b64 {%0,%1},%2;":"=f"(lo),"=f"(hi):"l"(p)); return lo+hi;
}
__device__ __forceinline__ void fma2(u64t &d, u64t a, u64t b){
  asm("fma.rn.f32x2 %0,%1,%2,%0;":"+l"(d):"l"(a),"l"(b));
}
__device__ __forceinline__ void lds2(u64t &a, u64t &b, u32t addr){
  asm volatile("ld.shared.v2.u64 {%0,%1},[%2];":"=l"(a),"=l"(b):"r"(addr));
}
__device__ __forceinline__ float sigm(float x){ return __fdividef(1.f, 1.f + __expf(-x)); }
__device__ __forceinline__ float tanh_f(float x){ return __fdividef(2.f, 1.f + __expf(-2.f*x)) - 1.f; }

__global__ __launch_bounds__(128, 1) void gru_kernel(
  const float* __restrict__ v_seq, const float* __restrict__ W_ih,
  const float* __restrict__ W_hh,  const float* __restrict__ b_ih,
  const float* __restrict__ b_hh,  const float* __restrict__ W_out,
  const float* __restrict__ b_out, float* __restrict__ xpred)
{
  extern __shared__ float sm[];
  const int tid  = threadIdx.x;
  const int lane = tid & 31, wid = tid >> 5;
  const int b0   = blockIdx.x * BT;
  const u32t sb  = smem_u32(sm);

  // ---- stage W_hh into SMEM, k-quad major: W4[kq][j] = W_hh[j][4kq..4kq+3]
  {
    const float4* whh4 = (const float4*)W_hh;
    float4* w4s = (float4*)sm;
    for (int idx = tid; idx < G3H*32; idx += 128){
      int kq = idx & 31;
      int j  = idx >> 5;
      w4s[kq*G3H + j] = whh4[j*32 + kq];     // coalesced global reads
    }
  }
  for (int i = tid; i < BT*HID; i += 128) sm[H_OFF + i] = 0.f;   // h0 = 0

  // ---- per-thread constants: thread t owns gate rows t (r), 128+t (z), 256+t (n)
  const int t_ = tid;
  const float bhr = b_hh[t_],        bhz = b_hh[HID+t_],        bhn = b_hh[2*HID+t_];
  const float bir = b_ih[t_],        biz = b_ih[HID+t_],        bin = b_ih[2*HID+t_];
  const float wr0 = W_ih[2*t_],            wr1 = W_ih[2*t_+1];
  const float wz0 = W_ih[2*(HID+t_)],      wz1 = W_ih[2*(HID+t_)+1];
  const float wn0 = W_ih[2*(2*HID+t_)],    wn1 = W_ih[2*(2*HID+t_)+1];
  const float wo0 = W_out[t_],             wo1 = W_out[HID+t_];

  // ---- v loader threads (tid < 14): (batch-in-tile, component)
  const int  bb   = tid >> 1, comp = tid & 1;
  const int  gb   = b0 + bb;
  const bool vldr = (tid < 2*BT) && (gb < BATCH);
  float boutv = 0.f;
  if (tid < 2*BT) boutv = b_out[comp];
  float vreg = 0.f;
  if (tid < 2*BT) sm[V_OFF + tid] = vldr ? v_seq[(gb*SEQ + 0)*2 + comp] : 0.f;
  if (vldr) vreg = v_seq[(gb*SEQ + 1)*2 + comp];

  float hreg[BT];
  #pragma unroll
  for (int b = 0; b < BT; b++) hreg[b] = 0.f;

  __syncthreads();

  for (int st = 0; st < SEQ; st++){
    const int cur = st & 1, nxt = cur ^ 1;

    // combine & store x_pred of previous step (overlaps with this step's GEMM)
    if (st > 0 && tid < 2*BT){
      float s = sm[P_OFF + tid] + sm[P_OFF + 14 + tid]
              + sm[P_OFF + 28 + tid] + sm[P_OFF + 42 + tid] + boutv;
      if (gb < BATCH) xpred[(gb*SEQ + (st-1))*2 + comp] = s;
    }

    // init packed accumulators: fold x-projection + biases for r,z; keep xn separate
    u64t accR[BT], accZ[BT], accN[BT]; float xnv[BT];
    #pragma unroll
    for (int b = 0; b < BT; b++){
      float v0 = sm[V_OFF + cur*14 + 2*b];
      float v1 = sm[V_OFF + cur*14 + 2*b + 1];
      accR[b] = pk2(bhr + bir + wr0*v0 + wr1*v1, 0.f);
      accZ[b] = pk2(bhz + biz + wz0*v0 + wz1*v1, 0.f);
      accN[b] = pk2(bhn, 0.f);
      xnv[b]  = bin + wn0*v0 + wn1*v1;
    }

    // ---- main GEMM: gh[b][{r,z,n} rows of i=t] += W_hh . h   (packed f32x2)
    u32t wbase = sb + (u32t)(t_*16);
    u32t hbase = sb + (u32t)(H_OFF*4);
    #pragma unroll 4
    for (int kq = 0; kq < 32; kq++){
      u64t wr01,wr23,wz01,wz23,wn01,wn23;
      lds2(wr01,wr23, wbase);
      lds2(wz01,wz23, wbase +   HID*16);
      lds2(wn01,wn23, wbase + 2*HID*16);
      #pragma unroll
      for (int b = 0; b < BT; b++){
        u64t h01,h23;
        lds2(h01,h23, hbase + (u32t)(b*HID*4));   // broadcast across warp
        fma2(accR[b],wr01,h01); fma2(accZ[b],wz01,h01); fma2(accN[b],wn01,h01);
        fma2(accR[b],wr23,h23); fma2(accZ[b],wz23,h23); fma2(accN[b],wn23,h23);
      }
      wbase += G3H*16;
      hbase += 16;
    }
    __syncthreads();   // all h_s reads done before overwrite

    if (tid < 2*BT) sm[V_OFF + nxt*14 + tid] = vreg;   // publish v for step st+1

    // ---- gates + h update + x_pred partials (all in-thread, i = t)
    #pragma unroll
    for (int b = 0; b < BT; b++){
      float r = sigm(psum(accR[b]));
      float z = sigm(psum(accZ[b]));
      float n = tanh_f(xnv[b] + r * psum(accN[b]));
      float h = (1.f - z)*n + z*hreg[b];
      hreg[b] = h;
      sm[H_OFF + b*HID + t_] = h;
      float p0 = wo0*h, p1 = wo1*h;
      #pragma unroll
      for (int off = 16; off > 0; off >>= 1){
        p0 += __shfl_xor_sync(0xffffffffu, p0, off);
        p1 += __shfl_xor_sync(0xffffffffu, p1, off);
      }
      if (lane == 0){
        sm[P_OFF + wid*14 + 2*b]     = p0;
        sm[P_OFF + wid*14 + 2*b + 1] = p1;
      }
    }

    if (vldr){ int s2 = st + 2; vreg = (s2 < SEQ) ? v_seq[(gb*SEQ + s2)*2 + comp] : 0.f; }
    __syncthreads();   // h_s / v_s / partials published
  }

  // final x_pred (st = SEQ-1)
  if (tid < 2*BT){
    float s = sm[P_OFF + tid] + sm[P_OFF + 14 + tid]
            + sm[P_OFF + 28 + tid] + sm[P_OFF + 42 + tid] + boutv;
    if (gb < BATCH) xpred[(gb*SEQ + (SEQ-1))*2 + comp] = s;
  }
}

// ---- kernel 2: residual MLP + physics violations (elementwise over B*S)
__global__ __launch_bounds__(256) void resid_kernel(
  const float* __restrict__ xpred, const float* __restrict__ x0,
  const float* __restrict__ v_seq,
  const float* __restrict__ W_r1, const float* __restrict__ b_r1,
  const float* __restrict__ W_r2, const float* __restrict__ b_r2,
  float* __restrict__ viol)
{
  __shared__ float w1[64*4], B1[64], w2[128], B2[2];
  int tid = threadIdx.x;
  if (tid < 256) w1[tid] = W_r1[tid];
  if (tid < 64)  B1[tid] = b_r1[tid];
  if (tid < 128) w2[tid] = W_r2[tid];
  if (tid < 2)   B2[tid] = b_r2[tid];
  __syncthreads();

  int idx = blockIdx.x*256 + tid;          // grid covers BATCH*SEQ exactly
  int b = idx >> 9, s = idx & (SEQ-1);
  float xp0, xp1;
  if (s == 0){ xp0 = x0[2*b];          xp1 = x0[2*b+1]; }
  else       { xp0 = xpred[(idx-1)*2]; xp1 = xpred[(idx-1)*2+1]; }
  float v0 = v_seq[idx*2], v1 = v_seq[idx*2+1];

  float a0 = B2[0], a1 = B2[1];
  #pragma unroll 8
  for (int h = 0; h < 64; h++){
    float hh = B1[h] + w1[4*h]*xp0 + w1[4*h+1]*xp1 + w1[4*h+2]*v0 + w1[4*h+3]*v1;
    hh = fmaxf(hh, 0.f);
    a0 += w2[h]*hh;
    a1 += w2[64+h]*hh;
  }
  float c0 = xpred[idx*2], c1 = xpred[idx*2+1];
  viol[idx*2]   = c0 - (xp0 + v0 + a0);
  viol[idx*2+1] = c1 - (xp1 + v1 + a1);
}

extern "C" void kernel_launch(void* const* d_in, const int* in_sizes, int n_in,
                              void* d_out, int out_size)
{
  const float* x0    = (const float*)d_in[0];
  const float* v_seq = (const float*)d_in[1];
  const float* W_ih  = (const float*)d_in[2];
  const float* W_hh  = (const float*)d_in[3];
  const float* b_ih  = (const float*)d_in[4];
  const float* b_hh  = (const float*)d_in[5];
  const float* W_out = (const float*)d_in[6];
  const float* b_out = (const float*)d_in[7];
  const float* W_r1  = (const float*)d_in[8];
  const float* b_r1  = (const float*)d_in[9];
  const float* W_r2  = (const float*)d_in[10];
  const float* b_r2  = (const float*)d_in[11];

  float* xp   = (float*)d_out;
  float* viol = xp + (size_t)BATCH*SEQ*2;

  cudaFuncSetAttribute(gru_kernel, cudaFuncAttributeMaxDynamicSharedMemorySize, SMEM_BYTES);
  gru_kernel<<<NCTA, 128, SMEM_BYTES>>>(v_seq, W_ih, W_hh, b_ih, b_hh, W_out, b_out, xp);
  resid_kernel<<<(BATCH*SEQ)/256, 256>>>(xp, x0, v_seq, W_r1, b_r1, W_r2, b_r2, viol);
}